// round 2
// baseline (speedup 1.0000x reference)
#include <cuda_runtime.h>
#include <math.h>

#define BATCH 16
#define LSEQ  1024
#define HDIM  1024
#define M1    (BATCH * LSEQ)   // 16384
#define N1    2048
#define KD    1024
#define NEGV  (-1000000000000.0f)
#define TRILV (1000000000000.0f)

#define BM 128
#define BN 128
#define BK 16
#define SST 136   // padded smem row stride (keeps float4 alignment: 136*4 = 544 = 34*16)

// Scratch (allocation-free per harness rules)
__device__ float g_q[(size_t)BATCH * LSEQ * HDIM];     // 64 MB
__device__ float g_k[(size_t)BATCH * LSEQ * HDIM];     // 64 MB
__device__ float g_bias[BATCH * 4 * LSEQ];             // 256 KB

// ---------------------------------------------------------------------------
// bias[b, h, l] = (hidden[b,l,:] . W2[:,h] + b2[h]) / 2     (h = 0..3)
// ---------------------------------------------------------------------------
__global__ __launch_bounds__(256) void bias_kernel(
    const float* __restrict__ hidden, const float* __restrict__ W2,
    const float* __restrict__ b2)
{
    int idx = blockIdx.x * 256 + threadIdx.x;          // b*L + l, grid is exact
    const float* h = hidden + (size_t)idx * HDIM;
    float a0 = 0.f, a1 = 0.f, a2 = 0.f, a3 = 0.f;
    for (int k = 0; k < HDIM; ++k) {
        float hv = h[k];
        float4 w = *(const float4*)&W2[k * 4];
        a0 = fmaf(hv, w.x, a0);
        a1 = fmaf(hv, w.y, a1);
        a2 = fmaf(hv, w.z, a2);
        a3 = fmaf(hv, w.w, a3);
    }
    int b = idx >> 10, l = idx & 1023;
    float* bp = g_bias + (size_t)b * 4 * LSEQ + l;
    bp[0 * LSEQ] = (a0 + b2[0]) * 0.5f;
    bp[1 * LSEQ] = (a1 + b2[1]) * 0.5f;
    bp[2 * LSEQ] = (a2 + b2[2]) * 0.5f;
    bp[3 * LSEQ] = (a3 + b2[3]) * 0.5f;
}

// ---------------------------------------------------------------------------
// GEMM1: C[16384, 2048] = hidden @ W1 + b1, epilogue applies RoPE and
// scatters even columns -> g_q, odd columns -> g_k.
//   q[2i]   = C[4i],   q[2i+1] = C[4i+2]
//   k[2i]   = C[4i+1], k[2i+1] = C[4i+3]
//   rope pair i uses angle l * 10000^(-2i/H)
// ---------------------------------------------------------------------------
__global__ __launch_bounds__(256, 2) void gemm1_rope_kernel(
    const float* __restrict__ A, const float* __restrict__ W,
    const float* __restrict__ b1)
{
    __shared__ float As[2][BK][SST];
    __shared__ float Bs[2][BK][SST];
    const int tid = threadIdx.x;
    const int tx = tid & 15;
    const int ty = tid >> 4;
    const int m0 = blockIdx.y * BM;
    const int n0 = blockIdx.x * BN;

    const int ar = tid >> 2;            // A loader: row 0..63 (+64 for it=1)
    const int ac = (tid & 3) << 2;      // A loader: k offset 0,4,8,12
    const int bk = tid >> 5;            // B loader: k row 0..7 (+8 for it=1)
    const int bn = (tid & 31) << 2;     // B loader: n offset 0..124

    float acc[8][8] = {};
    float4 pa[2], pb[2];

    // prologue: tile kt=0
    #pragma unroll
    for (int it = 0; it < 2; ++it) {
        pa[it] = *(const float4*)&A[(size_t)(m0 + ar + it * 64) * KD + ac];
        pb[it] = *(const float4*)&W[(size_t)(bk + it * 8) * N1 + n0 + bn];
    }
    #pragma unroll
    for (int it = 0; it < 2; ++it) {
        int r = ar + it * 64;
        As[0][ac + 0][r] = pa[it].x;
        As[0][ac + 1][r] = pa[it].y;
        As[0][ac + 2][r] = pa[it].z;
        As[0][ac + 3][r] = pa[it].w;
        *(float4*)&Bs[0][bk + it * 8][bn] = pb[it];
    }
    __syncthreads();

    int buf = 0;
    for (int kt = 0; kt < KD / BK; ++kt) {
        if (kt < KD / BK - 1) {
            int k0 = (kt + 1) * BK;
            #pragma unroll
            for (int it = 0; it < 2; ++it) {
                pa[it] = *(const float4*)&A[(size_t)(m0 + ar + it * 64) * KD + k0 + ac];
                pb[it] = *(const float4*)&W[(size_t)(k0 + bk + it * 8) * N1 + n0 + bn];
            }
        }
        #pragma unroll
        for (int kk = 0; kk < BK; ++kk) {
            float4 a0 = *(const float4*)&As[buf][kk][ty * 8];
            float4 a1 = *(const float4*)&As[buf][kk][ty * 8 + 4];
            float4 b0 = *(const float4*)&Bs[buf][kk][tx * 8];
            float4 b1v = *(const float4*)&Bs[buf][kk][tx * 8 + 4];
            float av[8] = {a0.x, a0.y, a0.z, a0.w, a1.x, a1.y, a1.z, a1.w};
            float bv[8] = {b0.x, b0.y, b0.z, b0.w, b1v.x, b1v.y, b1v.z, b1v.w};
            #pragma unroll
            for (int i = 0; i < 8; ++i)
                #pragma unroll
                for (int j = 0; j < 8; ++j)
                    acc[i][j] = fmaf(av[i], bv[j], acc[i][j]);
        }
        if (kt < KD / BK - 1) {
            int nb = buf ^ 1;
            #pragma unroll
            for (int it = 0; it < 2; ++it) {
                int r = ar + it * 64;
                As[nb][ac + 0][r] = pa[it].x;
                As[nb][ac + 1][r] = pa[it].y;
                As[nb][ac + 2][r] = pa[it].z;
                As[nb][ac + 3][r] = pa[it].w;
                *(float4*)&Bs[nb][bk + it * 8][bn] = pb[it];
            }
            __syncthreads();
        }
        buf ^= 1;
    }

    // ---- epilogue: bias add + RoPE + scatter to g_q / g_k ----
    const int cbase = n0 + tx * 8;      // multiple of 8
    const int ir0 = cbase >> 2;         // rope pair index for group 0
    double invd[2];
    #pragma unroll
    for (int g = 0; g < 2; ++g)
        invd[g] = exp((double)(ir0 + g) * (-2.0 * 9.210340371976184 / (double)HDIM));

    float b1loc[8];
    #pragma unroll
    for (int j = 0; j < 8; ++j) b1loc[j] = b1[cbase + j];

    #pragma unroll
    for (int i = 0; i < 8; ++i) {
        int m = m0 + ty * 8 + i;
        int bb = m >> 10;
        int l = m & 1023;
        float* qbase = g_q + ((size_t)bb * LSEQ + l) * HDIM;
        float* kbase = g_k + ((size_t)bb * LSEQ + l) * HDIM;
        #pragma unroll
        for (int g = 0; g < 2; ++g) {
            // match reference: emb computed in fp32, trig evaluated accurately
            float ef = (float)((double)l * invd[g]);
            double sd, cd;
            sincos((double)ef, &sd, &cd);
            float s = (float)sd, c = (float)cd;

            float q0 = acc[i][g * 4 + 0] + b1loc[g * 4 + 0];
            float k0 = acc[i][g * 4 + 1] + b1loc[g * 4 + 1];
            float q1 = acc[i][g * 4 + 2] + b1loc[g * 4 + 2];
            float k1 = acc[i][g * 4 + 3] + b1loc[g * 4 + 3];

            int ir = ir0 + g;
            float2 qo = make_float2(q0 * c - q1 * s, q1 * c + q0 * s);
            float2 ko = make_float2(k0 * c - k1 * s, k1 * c + k0 * s);
            *(float2*)&qbase[2 * ir] = qo;
            *(float2*)&kbase[2 * ir] = ko;
        }
    }
}

// ---------------------------------------------------------------------------
// GEMM2: per batch b, qk[m,n] = q[b,m,:] . k[b,n,:] / 32, then for t in {0,1}
//   v = qk + bias[b,2t,n] + bias[b,2t+1,m]; row/col token-type masks; tril.
// ---------------------------------------------------------------------------
__global__ __launch_bounds__(256, 2) void gemm2_kernel(
    const int* __restrict__ tt, float* __restrict__ out)
{
    __shared__ float As[2][BK][SST];
    __shared__ float Bs[2][BK][SST];
    const int tid = threadIdx.x;
    const int tx = tid & 15;
    const int ty = tid >> 4;
    const int b = blockIdx.z;
    const int m0 = blockIdx.y * BM;
    const int n0 = blockIdx.x * BN;
    const float* Q = g_q + (size_t)b * LSEQ * HDIM;
    const float* Km = g_k + (size_t)b * LSEQ * HDIM;

    const int ar = tid >> 2;
    const int ac = (tid & 3) << 2;

    float acc[8][8] = {};
    float4 pa[2], pb[2];

    #pragma unroll
    for (int it = 0; it < 2; ++it) {
        pa[it] = *(const float4*)&Q[(size_t)(m0 + ar + it * 64) * HDIM + ac];
        pb[it] = *(const float4*)&Km[(size_t)(n0 + ar + it * 64) * HDIM + ac];
    }
    #pragma unroll
    for (int it = 0; it < 2; ++it) {
        int r = ar + it * 64;
        As[0][ac + 0][r] = pa[it].x;  As[0][ac + 1][r] = pa[it].y;
        As[0][ac + 2][r] = pa[it].z;  As[0][ac + 3][r] = pa[it].w;
        Bs[0][ac + 0][r] = pb[it].x;  Bs[0][ac + 1][r] = pb[it].y;
        Bs[0][ac + 2][r] = pb[it].z;  Bs[0][ac + 3][r] = pb[it].w;
    }
    __syncthreads();

    int buf = 0;
    for (int kt = 0; kt < HDIM / BK; ++kt) {
        if (kt < HDIM / BK - 1) {
            int k0 = (kt + 1) * BK;
            #pragma unroll
            for (int it = 0; it < 2; ++it) {
                pa[it] = *(const float4*)&Q[(size_t)(m0 + ar + it * 64) * HDIM + k0 + ac];
                pb[it] = *(const float4*)&Km[(size_t)(n0 + ar + it * 64) * HDIM + k0 + ac];
            }
        }
        #pragma unroll
        for (int kk = 0; kk < BK; ++kk) {
            float4 a0 = *(const float4*)&As[buf][kk][ty * 8];
            float4 a1 = *(const float4*)&As[buf][kk][ty * 8 + 4];
            float4 b0 = *(const float4*)&Bs[buf][kk][tx * 8];
            float4 b1v = *(const float4*)&Bs[buf][kk][tx * 8 + 4];
            float av[8] = {a0.x, a0.y, a0.z, a0.w, a1.x, a1.y, a1.z, a1.w};
            float bv[8] = {b0.x, b0.y, b0.z, b0.w, b1v.x, b1v.y, b1v.z, b1v.w};
            #pragma unroll
            for (int i = 0; i < 8; ++i)
                #pragma unroll
                for (int j = 0; j < 8; ++j)
                    acc[i][j] = fmaf(av[i], bv[j], acc[i][j]);
        }
        if (kt < HDIM / BK - 1) {
            int nb = buf ^ 1;
            #pragma unroll
            for (int it = 0; it < 2; ++it) {
                int r = ar + it * 64;
                As[nb][ac + 0][r] = pa[it].x;  As[nb][ac + 1][r] = pa[it].y;
                As[nb][ac + 2][r] = pa[it].z;  As[nb][ac + 3][r] = pa[it].w;
                Bs[nb][ac + 0][r] = pb[it].x;  Bs[nb][ac + 1][r] = pb[it].y;
                Bs[nb][ac + 2][r] = pb[it].z;  Bs[nb][ac + 3][r] = pb[it].w;
            }
            __syncthreads();
        }
        buf ^= 1;
    }

    // ---- epilogue: scale, bias, masks, tril, write both t slices ----
    const float scale = 0.03125f;       // 1/sqrt(1024) = 1/32 exact
    const int nb0 = n0 + tx * 8;

    float mr[8], bO0[8], bO1[8];
    #pragma unroll
    for (int i = 0; i < 8; ++i) {
        int m = m0 + ty * 8 + i;
        mr[i]  = (float)tt[b * LSEQ + m];
        bO0[i] = g_bias[((size_t)b * 4 + 1) * LSEQ + m];
        bO1[i] = g_bias[((size_t)b * 4 + 3) * LSEQ + m];
    }
    float mc[8], bE0[8], bE1[8];
    #pragma unroll
    for (int j = 0; j < 8; ++j) {
        int n = nb0 + j;
        mc[j]  = (float)tt[b * LSEQ + n];
        bE0[j] = g_bias[((size_t)b * 4 + 0) * LSEQ + n];
        bE1[j] = g_bias[((size_t)b * 4 + 2) * LSEQ + n];
    }

    #pragma unroll
    for (int i = 0; i < 8; ++i) {
        int m = m0 + ty * 8 + i;
        float o0[8], o1[8];
        #pragma unroll
        for (int j = 0; j < 8; ++j) {
            int n = nb0 + j;
            float qk = acc[i][j] * scale;
            float v0 = qk + bE0[j] + bO0[i];
            float v1 = qk + bE1[j] + bO1[i];
            float rm = mr[i], cm = mc[j];
            v0 = v0 * rm + NEGV * (1.0f - rm);
            v0 = v0 * cm + NEGV * (1.0f - cm);
            v1 = v1 * rm + NEGV * (1.0f - rm);
            v1 = v1 * cm + NEGV * (1.0f - cm);
            if (m > n) { v0 -= TRILV; v1 -= TRILV; }
            o0[j] = v0;
            o1[j] = v1;
        }
        size_t r0 = ((size_t)(b * 2 + 0) * LSEQ + m) * LSEQ + nb0;
        size_t r1 = ((size_t)(b * 2 + 1) * LSEQ + m) * LSEQ + nb0;
        *(float4*)&out[r0]     = make_float4(o0[0], o0[1], o0[2], o0[3]);
        *(float4*)&out[r0 + 4] = make_float4(o0[4], o0[5], o0[6], o0[7]);
        *(float4*)&out[r1]     = make_float4(o1[0], o1[1], o1[2], o1[3]);
        *(float4*)&out[r1 + 4] = make_float4(o1[4], o1[5], o1[6], o1[7]);
    }
}

// ---------------------------------------------------------------------------
extern "C" void kernel_launch(void* const* d_in, const int* in_sizes, int n_in,
                              void* d_out, int out_size)
{
    const float* hidden = (const float*)d_in[0];
    const int*   tt     = (const int*)d_in[1];
    const float* W1     = (const float*)d_in[2];
    const float* b1     = (const float*)d_in[3];
    const float* W2     = (const float*)d_in[4];
    const float* b2     = (const float*)d_in[5];
    float* out = (float*)d_out;

    bias_kernel<<<M1 / 256, 256>>>(hidden, W2, b2);

    dim3 g1(N1 / BN, M1 / BM);           // 16 x 128
    gemm1_rope_kernel<<<g1, 256>>>(hidden, W1, b1);

    dim3 g2(LSEQ / BN, LSEQ / BM, BATCH); // 8 x 8 x 16
    gemm2_kernel<<<g2, 256>>>(tt, out);
}

// round 4
// speedup vs baseline: 5.2569x; 5.2569x over previous
#include <cuda_runtime.h>
#include <cuda_fp16.h>
#include <math.h>
#include <stdint.h>

#define BATCH 16
#define LSEQ  1024
#define HDIM  1024
#define NEGV  (-1000000000000.0f)
#define TRILV (1000000000000.0f)

// -------------------- scratch (allocation-free) --------------------
__device__ __half g_hbf[(size_t)BATCH * LSEQ * HDIM];   // hidden fp16 [M,K]
__device__ __half g_w1t[(size_t)2048 * 1024];           // W1^T fp16 [N,K]
__device__ __half g_q[(size_t)BATCH * LSEQ * HDIM];     // fp16 [B,L,H]
__device__ __half g_k[(size_t)BATCH * LSEQ * HDIM];
__device__ float  g_bias[BATCH * 4 * LSEQ];

// -------------------- helpers (baseline PTX ISA only) --------------------
__device__ __forceinline__ uint32_t smem_u32(const void* p) {
    uint32_t a;
    asm("{ .reg .u64 t; cvta.to.shared.u64 t, %1; cvt.u32.u64 %0, t; }" : "=r"(a) : "l"(p));
    return a;
}
__device__ __forceinline__ void cp16(uint32_t dst, const void* src) {
    asm volatile("cp.async.cg.shared.global [%0], [%1], 16;" :: "r"(dst), "l"(src));
}
__device__ __forceinline__ void cp_commit() { asm volatile("cp.async.commit_group;" ::: "memory"); }
__device__ __forceinline__ void ldsm4(uint32_t* r, uint32_t addr) {
    asm volatile("ldmatrix.sync.aligned.m8n8.x4.shared.b16 {%0,%1,%2,%3}, [%4];"
                 : "=r"(r[0]), "=r"(r[1]), "=r"(r[2]), "=r"(r[3]) : "r"(addr));
}
__device__ __forceinline__ void mma16816(float* d, const uint32_t* a, uint32_t b0, uint32_t b1) {
    asm volatile("mma.sync.aligned.m16n8k16.row.col.f32.f16.f16.f32 "
                 "{%0,%1,%2,%3}, {%4,%5,%6,%7}, {%8,%9}, {%0,%1,%2,%3};"
                 : "+f"(d[0]), "+f"(d[1]), "+f"(d[2]), "+f"(d[3])
                 : "r"(a[0]), "r"(a[1]), "r"(a[2]), "r"(a[3]), "r"(b0), "r"(b1));
}

#define STAGE_BYTES 32768               // A 16KB + B 16KB per stage
#define DYN_SMEM    (1024 + 3 * STAGE_BYTES)   // align slack + 3 stages (epilogue reuses)

// -------------------- shared mainloop --------------------
// acc[mf][nf][e] = (A[128,1024] @ B[128,1024]^T) 128x128 tile, fp16 in fp32 acc.
// Warp grid 2(m) x 4(n); warp tile 64x32; fragments per mma.m16n8k16.
__device__ __forceinline__ void gemm_mainloop(const __half* __restrict__ Ab,
                                              const __half* __restrict__ Bb,
                                              uint32_t sb, float acc[4][4][4])
{
    const int tid = threadIdx.x, lane = tid & 31, wid = tid >> 5;
    const int wm = wid >> 2, wn = wid & 3;

    // cp.async loader: row = tid>>1 (0..127), 4x16B chunks at c16 = (tid&1)*4 + i
    const int lrow = tid >> 1;
    const int lc0 = (tid & 1) * 4;
    const __half* ap = Ab + (size_t)lrow * 1024 + lc0 * 8;
    const __half* bp = Bb + (size_t)lrow * 1024 + lc0 * 8;
    uint32_t soff[4];
    #pragma unroll
    for (int i = 0; i < 4; ++i) {
        uint32_t off = lrow * 128 + (lc0 + i) * 16;
        soff[i] = off ^ ((off >> 3) & 0x70);
    }
    uint32_t stA[3], stB[3];
    #pragma unroll
    for (int s = 0; s < 3; ++s) { stA[s] = sb + s * STAGE_BYTES; stB[s] = stA[s] + 16384; }

    // prologue: tiles 0,1
    #pragma unroll
    for (int t = 0; t < 2; ++t) {
        #pragma unroll
        for (int i = 0; i < 4; ++i) {
            cp16(stA[t] + soff[i], ap + t * 64 + i * 8);
            cp16(stB[t] + soff[i], bp + t * 64 + i * 8);
        }
        cp_commit();
    }

    // ldmatrix addressing: lane -> (row = base + lane&15, colblk = lane>>4)
    const int lr = lane & 15, lhi = lane >> 4;
    const uint32_t xorterm = (uint32_t)(lr & 7) * 16;
    uint32_t aRow[4], bRow[2];
    #pragma unroll
    for (int mf = 0; mf < 4; ++mf) aRow[mf] = (uint32_t)(wm * 64 + mf * 16 + lr) * 128;
    #pragma unroll
    for (int nfp = 0; nfp < 2; ++nfp) bRow[nfp] = (uint32_t)(wn * 32 + nfp * 16 + lr) * 128;

    #pragma unroll 1
    for (int kt = 0; kt < 16; ++kt) {
        if (kt == 15) asm volatile("cp.async.wait_group 0;" ::: "memory");
        else          asm volatile("cp.async.wait_group 1;" ::: "memory");
        __syncthreads();

        if (kt < 14) {
            const int t = kt + 2;
            const int sl = t - (t / 3) * 3;
            #pragma unroll
            for (int i = 0; i < 4; ++i) {
                cp16(stA[sl] + soff[i], ap + t * 64 + i * 8);
                cp16(stB[sl] + soff[i], bp + t * 64 + i * 8);
            }
            cp_commit();
        }

        const int s = kt - (kt / 3) * 3;
        const uint32_t sA = stA[s], sB = stB[s];
        #pragma unroll
        for (int ks = 0; ks < 4; ++ks) {
            const uint32_t colbyte = ((uint32_t)(ks * 2 + lhi) * 16) ^ xorterm;
            uint32_t bfr[2][4];
            #pragma unroll
            for (int nfp = 0; nfp < 2; ++nfp) ldsm4(bfr[nfp], sB + bRow[nfp] + colbyte);
            #pragma unroll
            for (int mf = 0; mf < 4; ++mf) {
                uint32_t afr[4];
                ldsm4(afr, sA + aRow[mf] + colbyte);
                #pragma unroll
                for (int nf = 0; nf < 4; ++nf)
                    mma16816(acc[mf][nf], afr,
                             bfr[nf >> 1][nf & 1], bfr[nf >> 1][2 + (nf & 1)]);
            }
        }
    }
    __syncthreads();   // mainloop smem now reusable by epilogues
}

// -------------------- GEMM1: hidden @ W1 + b1, RoPE, scatter q/k --------------------
__global__ __launch_bounds__(256, 2) void gemm1_kernel(const float* __restrict__ b1v)
{
    extern __shared__ char smem_raw[];
    char* base = (char*)(((uintptr_t)smem_raw + 1023) & ~(uintptr_t)1023);
    const uint32_t sb = smem_u32(base);
    const int tid = threadIdx.x, lane = tid & 31, wid = tid >> 5;
    const int wm = wid >> 2, wn = wid & 3;
    const int m0 = blockIdx.y * 128, n0 = blockIdx.x * 128;

    float acc[4][4][4] = {};
    gemm_mainloop(g_hbf + (size_t)m0 * 1024, g_w1t + (size_t)n0 * 1024, sb, acc);

    // stage C tile to smem (raw acc; b1 added at read)
    float* Cb = (float*)base;      // [128][132]
    const int r0 = wm * 64 + (lane >> 2);
    const int c0l = wn * 32 + (lane & 3) * 2;
    #pragma unroll
    for (int mf = 0; mf < 4; ++mf)
        #pragma unroll
        for (int nf = 0; nf < 4; ++nf) {
            float* p = &Cb[(r0 + mf * 16) * 132 + c0l + nf * 8];
            *(float2*)p             = make_float2(acc[mf][nf][0], acc[mf][nf][1]);
            *(float2*)(p + 8 * 132) = make_float2(acc[mf][nf][2], acc[mf][nf][3]);
        }
    __syncthreads();

    // RoPE + scatter: one quad (4 cols) per thread-iter, coalesced half2 writes
    #pragma unroll 1
    for (int it = 0; it < 16; ++it) {
        const int w = it * 256 + tid;
        const int r = w >> 5, quad = w & 31;
        float4 v = *(float4*)&Cb[r * 132 + quad * 4];
        const int cb = n0 + quad * 4;
        const int ir = cb >> 2;
        const int m = m0 + r;
        const int l = m & 1023;
        const float inv = expf(-(float)ir * (2.0f * 9.210340371976184f / 1024.0f));
        float s, c;
        sincosf((float)l * inv, &s, &c);
        float q0 = v.x + b1v[cb + 0];
        float k0 = v.y + b1v[cb + 1];
        float q1 = v.z + b1v[cb + 2];
        float k1 = v.w + b1v[cb + 3];
        __half2 qh = __floats2half2_rn(q0 * c - q1 * s, q1 * c + q0 * s);
        __half2 kh = __floats2half2_rn(k0 * c - k1 * s, k1 * c + k0 * s);
        *(uint32_t*)&g_q[(size_t)m * 1024 + (cb >> 1)] = *reinterpret_cast<uint32_t*>(&qh);
        *(uint32_t*)&g_k[(size_t)m * 1024 + (cb >> 1)] = *reinterpret_cast<uint32_t*>(&kh);
    }
}

// -------------------- GEMM2: q @ k^T, scale + bias + masks + tril --------------------
__global__ __launch_bounds__(256, 2) void gemm2_kernel(const int* __restrict__ tt,
                                                       float* __restrict__ out)
{
    extern __shared__ char smem_raw[];
    __shared__ float s_tb[768];   // bE0[128] bE1[128] mc[128] | bO0[128] bO1[128] mr[128]
    char* base = (char*)(((uintptr_t)smem_raw + 1023) & ~(uintptr_t)1023);
    const uint32_t sb = smem_u32(base);
    const int tid = threadIdx.x, lane = tid & 31, wid = tid >> 5;
    const int wm = wid >> 2, wn = wid & 3;
    const int b = blockIdx.z, m0 = blockIdx.y * 128, n0 = blockIdx.x * 128;

    float acc[4][4][4] = {};
    gemm_mainloop(g_q + ((size_t)b << 20) + (size_t)m0 * 1024,
                  g_k + ((size_t)b << 20) + (size_t)n0 * 1024, sb, acc);

    if (tid < 128) {
        const int n = n0 + tid;
        s_tb[tid]       = g_bias[b * 4096 + n];
        s_tb[128 + tid] = g_bias[b * 4096 + 2048 + n];
        s_tb[256 + tid] = (float)tt[(b << 10) + n];
    } else {
        const int r = tid - 128, m = m0 + r;
        s_tb[384 + r] = g_bias[b * 4096 + 1024 + m];
        s_tb[512 + r] = g_bias[b * 4096 + 3072 + m];
        s_tb[640 + r] = (float)tt[(b << 10) + m];
    }
    __syncthreads();

    const float scale = 0.03125f;   // 1/sqrt(1024)
    #pragma unroll
    for (int mf = 0; mf < 4; ++mf) {
        #pragma unroll
        for (int h = 0; h < 2; ++h) {
            const int Rl = wm * 64 + mf * 16 + (lane >> 2) + h * 8;
            const int m = m0 + Rl;
            const float bo0 = s_tb[384 + Rl], bo1 = s_tb[512 + Rl], rm = s_tb[640 + Rl];
            float* o0 = out + ((size_t)(b * 2) * 1024 + m) * 1024 + n0;
            float* o1 = o0 + (size_t)1024 * 1024;
            #pragma unroll
            for (int nf = 0; nf < 4; ++nf) {
                const int Cl = wn * 32 + nf * 8 + (lane & 3) * 2;
                float2 r0v, r1v;
                #pragma unroll
                for (int e = 0; e < 2; ++e) {
                    const int nl = Cl + e;
                    const int n = n0 + nl;
                    const float v = acc[mf][nf][h * 2 + e] * scale;
                    const float keep = rm * s_tb[256 + nl];
                    float v0 = v + s_tb[nl]       + bo0;
                    float v1 = v + s_tb[128 + nl] + bo1;
                    v0 = (keep != 0.0f) ? v0 : NEGV;
                    v1 = (keep != 0.0f) ? v1 : NEGV;
                    if (m > n) { v0 -= TRILV; v1 -= TRILV; }
                    (&r0v.x)[e] = v0;
                    (&r1v.x)[e] = v1;
                }
                *(float2*)(o0 + Cl) = r0v;
                *(float2*)(o1 + Cl) = r1v;
            }
        }
    }
}

// -------------------- prep kernels --------------------
__global__ __launch_bounds__(256) void convert_hidden(const float* __restrict__ hidden)
{
    const size_t i = ((size_t)blockIdx.x * 256 + threadIdx.x) * 8;
    float4 a = *(const float4*)&hidden[i];
    float4 bq = *(const float4*)&hidden[i + 4];
    __half2 h0 = __floats2half2_rn(a.x, a.y);
    __half2 h1 = __floats2half2_rn(a.z, a.w);
    __half2 h2 = __floats2half2_rn(bq.x, bq.y);
    __half2 h3 = __floats2half2_rn(bq.z, bq.w);
    uint4 o;
    o.x = *reinterpret_cast<uint32_t*>(&h0);
    o.y = *reinterpret_cast<uint32_t*>(&h1);
    o.z = *reinterpret_cast<uint32_t*>(&h2);
    o.w = *reinterpret_cast<uint32_t*>(&h3);
    *(uint4*)&g_hbf[i] = o;
}

__global__ __launch_bounds__(256) void transpose_w1(const float* __restrict__ W1)
{
    __shared__ float tile[32][33];
    const int tx = threadIdx.x & 31, ty = threadIdx.x >> 5;   // 32x8
    const int nb = blockIdx.x * 32, kb = blockIdx.y * 32;
    #pragma unroll
    for (int i = 0; i < 4; ++i)
        tile[ty + i * 8][tx] = W1[(size_t)(kb + ty + i * 8) * 2048 + nb + tx];
    __syncthreads();
    #pragma unroll
    for (int i = 0; i < 4; ++i)
        g_w1t[(size_t)(nb + ty + i * 8) * 1024 + kb + tx] = __float2half_rn(tile[tx][ty + i * 8]);
}

__global__ __launch_bounds__(256) void bias2_kernel(const float* __restrict__ hidden,
                                                    const float* __restrict__ W2,
                                                    const float* __restrict__ b2)
{
    const int wid = threadIdx.x >> 5, lane = threadIdx.x & 31;
    const int rowm = blockIdx.x * 8 + wid;                    // 0..16383
    const float* h = hidden + (size_t)rowm * 1024;
    float a0 = 0.f, a1 = 0.f, a2 = 0.f, a3 = 0.f;
    #pragma unroll 8
    for (int i = 0; i < 32; ++i) {
        const int k = i * 32 + lane;
        const float hv = h[k];
        float4 w = *(const float4*)&W2[k * 4];
        a0 = fmaf(hv, w.x, a0);
        a1 = fmaf(hv, w.y, a1);
        a2 = fmaf(hv, w.z, a2);
        a3 = fmaf(hv, w.w, a3);
    }
    #pragma unroll
    for (int off = 16; off > 0; off >>= 1) {
        a0 += __shfl_xor_sync(0xFFFFFFFF, a0, off);
        a1 += __shfl_xor_sync(0xFFFFFFFF, a1, off);
        a2 += __shfl_xor_sync(0xFFFFFFFF, a2, off);
        a3 += __shfl_xor_sync(0xFFFFFFFF, a3, off);
    }
    if (lane == 0) {
        const int bb = rowm >> 10, l = rowm & 1023;
        float* bp = g_bias + (size_t)bb * 4096 + l;
        bp[0]    = (a0 + b2[0]) * 0.5f;
        bp[1024] = (a1 + b2[1]) * 0.5f;
        bp[2048] = (a2 + b2[2]) * 0.5f;
        bp[3072] = (a3 + b2[3]) * 0.5f;
    }
}

// -------------------- launch --------------------
extern "C" void kernel_launch(void* const* d_in, const int* in_sizes, int n_in,
                              void* d_out, int out_size)
{
    const float* hidden = (const float*)d_in[0];
    const int*   tt     = (const int*)d_in[1];
    const float* W1     = (const float*)d_in[2];
    const float* b1     = (const float*)d_in[3];
    const float* W2     = (const float*)d_in[4];
    const float* b2     = (const float*)d_in[5];
    float* out = (float*)d_out;

    cudaFuncSetAttribute(gemm1_kernel, cudaFuncAttributeMaxDynamicSharedMemorySize, DYN_SMEM);
    cudaFuncSetAttribute(gemm2_kernel, cudaFuncAttributeMaxDynamicSharedMemorySize, DYN_SMEM);

    convert_hidden<<<8192, 256>>>(hidden);
    transpose_w1<<<dim3(64, 32), dim3(256)>>>(W1);
    bias2_kernel<<<2048, 256>>>(hidden, W2, b2);

    dim3 g1(16, 128);                 // N/128 x M/128
    gemm1_kernel<<<g1, 256, DYN_SMEM>>>(b1);

    dim3 g2(8, 8, BATCH);             // N/128 x M/128 x B
    gemm2_kernel<<<g2, 256, DYN_SMEM>>>(tt, out);
}